// round 11
// baseline (speedup 1.0000x reference)
#include <cuda_runtime.h>
#include <cstdint>
#include <cstddef>

// x:   [B=8192, F=32, E=64] f32
// W:   [E=64, E=64] f32
// out: [B, P=496, E=64] f32,  out[b,p,:] = (x[b,i_p,:] @ W) * x[b,j_p,:]
// (i_p, j_p) = triu_indices(32, k=1), row-major pair order.

#define BB 8192
#define FF 32
#define EE 64
#define PP 496
#define NV4 (PP * (EE/4)) // 7936 float4 per batch row
#define NTHREADS 512
#define ROWS_PER_BLK 2

// pairs before row i: sum_{t<i} (31-t) = 31*i - i*(i-1)/2
__device__ __forceinline__ int rowstart(int i) {
    return 31 * i - (i * (i - 1)) / 2;
}

__device__ __forceinline__ float4 fmul4(float4 a, float4 c) {
    float4 r;
    r.x = a.x * c.x; r.y = a.y * c.y; r.z = a.z * c.z; r.w = a.w * c.w;
    return r;
}

// Store one batch row with 16 groups of 16 lanes (g16 in 0..15): group owns
// rows i1=g16 (31-g16 pairs) and i2=30-g16 (g16+1 pairs); g16==15 owns only
// row 15 (balanced: 32 pairs/group). Inner body: 1 LDS.128 + 1 STG.128;
// each group streams sequential 256B pair records.
__device__ __forceinline__ void store_rows(const float4* __restrict__ xw4,
                                           const float4* __restrict__ xs4,
                                           float4* __restrict__ og,
                                           int g16, int v)
{
    {
        const int i = g16;
        const float4 a = xw4[i * 16 + v];
        float4* o = og + (ptrdiff_t)(rowstart(i) - i - 1) * 16 + v;
        #pragma unroll 4
        for (int j = i + 1; j < FF; ++j)
            __stcs(o + j * 16, fmul4(a, xs4[j * 16 + v]));
    }
    if (g16 < 15) {
        const int i = 30 - g16;
        const float4 a = xw4[i * 16 + v];
        float4* o = og + (ptrdiff_t)(rowstart(i) - i - 1) * 16 + v;
        #pragma unroll 4
        for (int j = i + 1; j < FF; ++j)
            __stcs(o + j * 16, fmul4(a, xs4[j * 16 + v]));
    }
}

__global__ __launch_bounds__(NTHREADS)
void bilinear_kernel(const float* __restrict__ x,
                     const float* __restrict__ W,
                     float* __restrict__ out)
{
    // 48 KB smem: dedicated xw buffer -> no mid-matmul barrier (R10 win),
    // 512 threads -> high store concurrency (R7 win). 4 CTAs/SM fits.
    __shared__ float xs[ROWS_PER_BLK * FF * EE]; // 16 KB : x[b0], x[b0+1]
    __shared__ float ws[EE * EE];                // 16 KB : W
    __shared__ float xw[ROWS_PER_BLK * FF * EE]; // 16 KB : xw[0], xw[1]

    const int tid = threadIdx.x;
    const int b0  = blockIdx.x * ROWS_PER_BLK;

    // ---- load x rows (1024 float4) and W (1024 float4) into SMEM ----
    {
        const float4* xg = reinterpret_cast<const float4*>(x) + (size_t)b0 * (FF * EE / 4);
        float4* xs4 = reinterpret_cast<float4*>(xs);
        #pragma unroll
        for (int q = tid; q < ROWS_PER_BLK * FF * EE / 4; q += NTHREADS)
            xs4[q] = xg[q];

        const float4* wg = reinterpret_cast<const float4*>(W);
        float4* ws4 = reinterpret_cast<float4*>(ws);
        #pragma unroll
        for (int q = tid; q < EE * EE / 4; q += NTHREADS)
            ws4[q] = wg[q];
    }

    __syncthreads();

    // ---- matmul: xw[r][f][e] = sum_k xs[r][f][k] * W[k][e] ----
    // 512 threads: 1 f-row x 4 e-cols x 2 batch rows each (8 acc floats).
    const int e0 = (tid & 15) * 4;
    const int f  = tid >> 4;           // 0..31
    {
        float4 a0 = make_float4(0.f, 0.f, 0.f, 0.f);
        float4 a1 = make_float4(0.f, 0.f, 0.f, 0.f);

        const float* xr0 = xs +           f * EE;
        const float* xr1 = xs + FF * EE + f * EE;

        #pragma unroll 8
        for (int k = 0; k < EE; ++k) {
            const float4 w = *reinterpret_cast<const float4*>(&ws[k * EE + e0]);
            const float x0 = xr0[k];
            const float x1 = xr1[k];
            a0.x += x0 * w.x; a0.y += x0 * w.y; a0.z += x0 * w.z; a0.w += x0 * w.w;
            a1.x += x1 * w.x; a1.y += x1 * w.y; a1.z += x1 * w.z; a1.w += x1 * w.w;
        }

        *reinterpret_cast<float4*>(&xw[          f * EE + e0]) = a0;
        *reinterpret_cast<float4*>(&xw[FF * EE + f * EE + e0]) = a1;
    }

    __syncthreads();  // single barrier between compute and store

    // ---- store phase ----
    // 32 groups of 16 lanes: groups 0..15 -> batch row 0, 16..31 -> batch row 1.
    {
        const int v   = tid & 15;
        const int g   = tid >> 4;       // 0..31
        const int r   = g >> 4;         // batch row select
        const int g16 = g & 15;

        float4* og = reinterpret_cast<float4*>(out) + (size_t)(b0 + r) * NV4;

        store_rows(reinterpret_cast<const float4*>(xw + r * FF * EE),
                   reinterpret_cast<const float4*>(xs + r * FF * EE),
                   og, g16, v);
    }
}

extern "C" void kernel_launch(void* const* d_in, const int* in_sizes, int n_in,
                              void* d_out, int out_size)
{
    const float* x = (const float*)d_in[0]; // [8192, 32, 64]
    const float* W = (const float*)d_in[1]; // [64, 64]
    float* out = (float*)d_out;             // [8192, 496, 64]
    (void)in_sizes; (void)n_in; (void)out_size;

    bilinear_kernel<<<BB / ROWS_PER_BLK, NTHREADS>>>(x, W, out);
}

// round 12
// speedup vs baseline: 1.0105x; 1.0105x over previous
#include <cuda_runtime.h>
#include <cstdint>
#include <cstddef>

// x:   [B=8192, F=32, E=64] f32
// W:   [E=64, E=64] f32
// out: [B, P=496, E=64] f32,  out[b,p,:] = (x[b,i_p,:] @ W) * x[b,j_p,:]
// (i_p, j_p) = triu_indices(32, k=1), row-major pair order.
//
// Final (locked) kernel — R10 configuration, best measured:
//   kernel 167.1us, e2e 170.1us, HBM 6273 GB/s (~98% of achievable write BW;
//   output traffic 1.04 GB is mandated by the problem, so this is roofline).

#define BB 8192
#define FF 32
#define EE 64
#define PP 496
#define NV4 (PP * (EE/4)) // 7936 float4 per batch row
#define NTHREADS 256
#define ROWS_PER_BLK 2

// pairs before row i: sum_{t<i} (31-t) = 31*i - i*(i-1)/2
__device__ __forceinline__ int rowstart(int i) {
    return 31 * i - (i * (i - 1)) / 2;
}

__device__ __forceinline__ float4 fmul4(float4 a, float4 c) {
    float4 r;
    r.x = a.x * c.x; r.y = a.y * c.y; r.z = a.z * c.z; r.w = a.w * c.w;
    return r;
}

// Store one batch row: 16 groups of 16 lanes; group g owns rows i1=g
// (31-g pairs) and i2=30-g (g+1 pairs); g==15 owns only row 15 (balanced:
// 32 pairs/group). xw[i] is register-cached -> inner body is exactly
// 1 LDS.128 + 1 STG.128 per output float4; each group streams sequential
// 256B pair records (8KB region) -> fully coalesced streaming stores.
__device__ __forceinline__ void store_rows(const float4* __restrict__ xw4,
                                           const float4* __restrict__ xs4,
                                           float4* __restrict__ og,
                                           int g, int v)
{
    {
        const int i = g;
        const float4 a = xw4[i * 16 + v];
        float4* o = og + (ptrdiff_t)(rowstart(i) - i - 1) * 16 + v;
        #pragma unroll 4
        for (int j = i + 1; j < FF; ++j)
            __stcs(o + j * 16, fmul4(a, xs4[j * 16 + v]));
    }
    if (g < 15) {
        const int i = 30 - g;
        const float4 a = xw4[i * 16 + v];
        float4* o = og + (ptrdiff_t)(rowstart(i) - i - 1) * 16 + v;
        #pragma unroll 4
        for (int j = i + 1; j < FF; ++j)
            __stcs(o + j * 16, fmul4(a, xs4[j * 16 + v]));
    }
}

__global__ __launch_bounds__(NTHREADS)
void bilinear_kernel(const float* __restrict__ x,
                     const float* __restrict__ W,
                     float* __restrict__ out)
{
    // 48 KB smem; dedicated xw buffer -> single barrier between compute and
    // store (no mid-matmul barrier). 4 CTAs/SM (reg-limited), occ ~46% —
    // measured sufficient to saturate the HBM write stream.
    __shared__ float xs[ROWS_PER_BLK * FF * EE]; // 16 KB : x[b0], x[b0+1]
    __shared__ float ws[EE * EE];                // 16 KB : W
    __shared__ float xw[ROWS_PER_BLK * FF * EE]; // 16 KB : xw[0], xw[1]

    const int tid = threadIdx.x;
    const int b0  = blockIdx.x * ROWS_PER_BLK;

    // ---- load x rows (1024 float4) and W (1024 float4) into SMEM ----
    {
        const float4* xg = reinterpret_cast<const float4*>(x) + (size_t)b0 * (FF * EE / 4);
        float4* xs4 = reinterpret_cast<float4*>(xs);
        #pragma unroll
        for (int q = tid; q < ROWS_PER_BLK * FF * EE / 4; q += NTHREADS)
            xs4[q] = xg[q];

        const float4* wg = reinterpret_cast<const float4*>(W);
        float4* ws4 = reinterpret_cast<float4*>(ws);
        #pragma unroll
        for (int q = tid; q < EE * EE / 4; q += NTHREADS)
            ws4[q] = wg[q];
    }

    __syncthreads();

    // ---- matmul: xw[r][f][e] = sum_k xs[r][f][k] * W[k][e] ----
    // 256 threads: 2 f-rows x 4 e-cols x 2 batch rows each; every w float4
    // feeds 4 FMA4s (W SMEM traffic amortized over 2 batch rows).
    const int e0 = (tid & 15) * 4;
    const int f0 = (tid >> 4) * 2;
    {
        float4 a00 = make_float4(0.f, 0.f, 0.f, 0.f);
        float4 a01 = make_float4(0.f, 0.f, 0.f, 0.f);
        float4 a10 = make_float4(0.f, 0.f, 0.f, 0.f);
        float4 a11 = make_float4(0.f, 0.f, 0.f, 0.f);

        const float* xs0 = xs;
        const float* xs1 = xs + FF * EE;

        #pragma unroll 8
        for (int k = 0; k < EE; ++k) {
            const float4 w = *reinterpret_cast<const float4*>(&ws[k * EE + e0]);
            const float x00 = xs0[ f0      * EE + k];
            const float x01 = xs0[(f0 + 1) * EE + k];
            const float x10 = xs1[ f0      * EE + k];
            const float x11 = xs1[(f0 + 1) * EE + k];
            a00.x += x00 * w.x; a00.y += x00 * w.y; a00.z += x00 * w.z; a00.w += x00 * w.w;
            a01.x += x01 * w.x; a01.y += x01 * w.y; a01.z += x01 * w.z; a01.w += x01 * w.w;
            a10.x += x10 * w.x; a10.y += x10 * w.y; a10.z += x10 * w.z; a10.w += x10 * w.w;
            a11.x += x11 * w.x; a11.y += x11 * w.y; a11.z += x11 * w.z; a11.w += x11 * w.w;
        }

        *reinterpret_cast<float4*>(&xw[          f0      * EE + e0]) = a00;
        *reinterpret_cast<float4*>(&xw[         (f0 + 1) * EE + e0]) = a01;
        *reinterpret_cast<float4*>(&xw[FF * EE +  f0      * EE + e0]) = a10;
        *reinterpret_cast<float4*>(&xw[FF * EE + (f0 + 1) * EE + e0]) = a11;
    }

    __syncthreads();  // single barrier between compute and store

    // ---- store phase: out[b,p,e] = xw[i_p][e] * xs[j_p][e], both rows ----
    {
        const int v = tid & 15;
        const int g = tid >> 4;

        float4* og0 = reinterpret_cast<float4*>(out) + (size_t)b0 * NV4;

        store_rows(reinterpret_cast<const float4*>(xw),
                   reinterpret_cast<const float4*>(xs), og0, g, v);
        store_rows(reinterpret_cast<const float4*>(xw + FF * EE),
                   reinterpret_cast<const float4*>(xs + FF * EE), og0 + NV4, g, v);
    }
}

extern "C" void kernel_launch(void* const* d_in, const int* in_sizes, int n_in,
                              void* d_out, int out_size)
{
    const float* x = (const float*)d_in[0]; // [8192, 32, 64]
    const float* W = (const float*)d_in[1]; // [64, 64]
    float* out = (float*)d_out;             // [8192, 496, 64]
    (void)in_sizes; (void)n_in; (void)out_size;

    bilinear_kernel<<<BB / ROWS_PER_BLK, NTHREADS>>>(x, W, out);
}

// round 13
// speedup vs baseline: 1.0149x; 1.0043x over previous
#include <cuda_runtime.h>
#include <cstdint>
#include <cstddef>

// x:   [B=8192, F=32, E=64] f32
// W:   [E=64, E=64] f32
// out: [B, P=496, E=64] f32,  out[b,p,:] = (x[b,i_p,:] @ W) * x[b,j_p,:]
// (i_p, j_p) = triu_indices(32, k=1), row-major pair order.
//
// R10 configuration (best measured: 167.1us kernel / 170.1us e2e,
// 6273 GB/s ~ 98% of achievable write BW) with interleaved dual-row
// store streams (deeper per-thread store MLP).

#define BB 8192
#define FF 32
#define EE 64
#define PP 496
#define NV4 (PP * (EE/4)) // 7936 float4 per batch row
#define NTHREADS 256
#define ROWS_PER_BLK 2

// pairs before row i: sum_{t<i} (31-t) = 31*i - i*(i-1)/2
__device__ __forceinline__ int rowstart(int i) {
    return 31 * i - (i * (i - 1)) / 2;
}

__device__ __forceinline__ float4 fmul4(float4 a, float4 c) {
    float4 r;
    r.x = a.x * c.x; r.y = a.y * c.y; r.z = a.z * c.z; r.w = a.w * c.w;
    return r;
}

// Store one batch row: 16 groups of 16 lanes; group g owns rows i1=g
// (pairs j=g+1..31) and i2=30-g (pairs j=31-g..31); g==15 owns only row 15.
// The two streams are INTERLEAVED and fully unrolled: each unrolled step
// issues up to two independent LDS.128+STG.128 pairs (different rows,
// independent addresses) -> deeper store MLP per thread, no loop-carried
// issue dependency. Group writes remain sequential 256B pair records.
__device__ __forceinline__ void store_rows(const float4* __restrict__ xw4,
                                           const float4* __restrict__ xs4,
                                           float4* __restrict__ og,
                                           int g, int v)
{
    const int i1 = g;
    const int i2 = 30 - g;                   // g==15 -> i2==15 (same as i1; masked below)
    const bool two = (g < 15);

    const float4 a1 = xw4[i1 * 16 + v];
    const float4 a2 = xw4[i2 * 16 + v];

    float4* o1 = og + (ptrdiff_t)(rowstart(i1) - i1 - 1) * 16 + v;
    float4* o2 = og + (ptrdiff_t)(rowstart(i2) - i2 - 1) * 16 + v;

    // j domain: row i1 active for j > i1 (= g), row i2 active for j > i2 (= 30-g).
    #pragma unroll
    for (int j = 1; j < FF; ++j) {
        if (j > i1) {
            const float4 c = xs4[j * 16 + v];
            __stcs(o1 + j * 16, fmul4(a1, c));
        }
        if (two && j > i2) {
            const float4 c = xs4[j * 16 + v];
            __stcs(o2 + j * 16, fmul4(a2, c));
        }
    }
}

__global__ __launch_bounds__(NTHREADS)
void bilinear_kernel(const float* __restrict__ x,
                     const float* __restrict__ W,
                     float* __restrict__ out)
{
    // 48 KB smem; dedicated xw buffer -> single barrier between compute and
    // store. 4 CTAs/SM, occ ~46% — measured sufficient to saturate HBM writes.
    __shared__ float xs[ROWS_PER_BLK * FF * EE]; // 16 KB : x[b0], x[b0+1]
    __shared__ float ws[EE * EE];                // 16 KB : W
    __shared__ float xw[ROWS_PER_BLK * FF * EE]; // 16 KB : xw[0], xw[1]

    const int tid = threadIdx.x;
    const int b0  = blockIdx.x * ROWS_PER_BLK;

    // ---- load x rows (1024 float4) and W (1024 float4) into SMEM ----
    {
        const float4* xg = reinterpret_cast<const float4*>(x) + (size_t)b0 * (FF * EE / 4);
        float4* xs4 = reinterpret_cast<float4*>(xs);
        #pragma unroll
        for (int q = tid; q < ROWS_PER_BLK * FF * EE / 4; q += NTHREADS)
            xs4[q] = xg[q];

        const float4* wg = reinterpret_cast<const float4*>(W);
        float4* ws4 = reinterpret_cast<float4*>(ws);
        #pragma unroll
        for (int q = tid; q < EE * EE / 4; q += NTHREADS)
            ws4[q] = wg[q];
    }

    __syncthreads();

    // ---- matmul: xw[r][f][e] = sum_k xs[r][f][k] * W[k][e] ----
    // 256 threads: 2 f-rows x 4 e-cols x 2 batch rows each; every w float4
    // feeds 4 FMA4s (W SMEM traffic amortized over 2 batch rows).
    const int e0 = (tid & 15) * 4;
    const int f0 = (tid >> 4) * 2;
    {
        float4 a00 = make_float4(0.f, 0.f, 0.f, 0.f);
        float4 a01 = make_float4(0.f, 0.f, 0.f, 0.f);
        float4 a10 = make_float4(0.f, 0.f, 0.f, 0.f);
        float4 a11 = make_float4(0.f, 0.f, 0.f, 0.f);

        const float* xs0 = xs;
        const float* xs1 = xs + FF * EE;

        #pragma unroll 8
        for (int k = 0; k < EE; ++k) {
            const float4 w = *reinterpret_cast<const float4*>(&ws[k * EE + e0]);
            const float x00 = xs0[ f0      * EE + k];
            const float x01 = xs0[(f0 + 1) * EE + k];
            const float x10 = xs1[ f0      * EE + k];
            const float x11 = xs1[(f0 + 1) * EE + k];
            a00.x += x00 * w.x; a00.y += x00 * w.y; a00.z += x00 * w.z; a00.w += x00 * w.w;
            a01.x += x01 * w.x; a01.y += x01 * w.y; a01.z += x01 * w.z; a01.w += x01 * w.w;
            a10.x += x10 * w.x; a10.y += x10 * w.y; a10.z += x10 * w.z; a10.w += x10 * w.w;
            a11.x += x11 * w.x; a11.y += x11 * w.y; a11.z += x11 * w.z; a11.w += x11 * w.w;
        }

        *reinterpret_cast<float4*>(&xw[          f0      * EE + e0]) = a00;
        *reinterpret_cast<float4*>(&xw[         (f0 + 1) * EE + e0]) = a01;
        *reinterpret_cast<float4*>(&xw[FF * EE +  f0      * EE + e0]) = a10;
        *reinterpret_cast<float4*>(&xw[FF * EE + (f0 + 1) * EE + e0]) = a11;
    }

    __syncthreads();  // single barrier between compute and store

    // ---- store phase: out[b,p,e] = xw[i_p][e] * xs[j_p][e], both rows ----
    {
        const int v = tid & 15;
        const int g = tid >> 4;

        float4* og0 = reinterpret_cast<float4*>(out) + (size_t)b0 * NV4;

        store_rows(reinterpret_cast<const float4*>(xw),
                   reinterpret_cast<const float4*>(xs), og0, g, v);
        store_rows(reinterpret_cast<const float4*>(xw + FF * EE),
                   reinterpret_cast<const float4*>(xs + FF * EE), og0 + NV4, g, v);
    }
}

extern "C" void kernel_launch(void* const* d_in, const int* in_sizes, int n_in,
                              void* d_out, int out_size)
{
    const float* x = (const float*)d_in[0]; // [8192, 32, 64]
    const float* W = (const float*)d_in[1]; // [64, 64]
    float* out = (float*)d_out;             // [8192, 496, 64]
    (void)in_sizes; (void)n_in; (void)out_size;

    bilinear_kernel<<<BB / ROWS_PER_BLK, NTHREADS>>>(x, W, out);
}